// round 6
// baseline (speedup 1.0000x reference)
#include <cuda_runtime.h>
#include <cuda_fp16.h>
#include <cstdint>

#define NN 100000
#define EE 1600000
#define FD 128
#define CHUNK 1024
#define NCH ((NN + CHUNK - 1) / CHUNK)   // 98

// node chunking for the spmm1/gemm1 pipeline (must be multiple of 128)
#define NODES_C0 50048
#define GBLK_C0 (NODES_C0 / 128)         // 391

// ---------------- device scratch (static, no allocation) ----------------
__device__ int      g_cnt[4][NN];          // 0: out_i, 1: in_i, 2: out_b, 3: in_b
__device__ float    g_norm[4][NN];         // rsqrt(max(cnt,1))
__device__ int      g_rowptr[2][NN + 1];   // CSR by dst: 0=interacts, 1=behave
__device__ int      g_cur[2][NN];          // write cursors (init = rowptr)
__device__ int      g_col[2][EE];          // src indices per CSR slot
__device__ int      g_csums[2][NCH];
__device__ __half2  g_H1h[NN * 64];        // (x@W1_i)*nout_i  (fp16, gathered); reused for H@W2
__device__ __half2  g_H1Bh[NN * 64];       // (x@W1_b)*nout_b  (fp16, gathered)
__device__ float    g_H[NN * FD];          // conv1 output fp32, pre-scaled by nout_i
// W packed into mma.sync m16n8k16 f16 B-fragment order (half2 words), fp16-split:
// [0/1]: W1i hi/lo, [2/3]: W1b hi/lo, [4/5]: W2 hi/lo. 8192 u32 each.
__device__ uint32_t g_Wp[6][FD * FD / 2];

// ---------------- helpers ----------------
__device__ __forceinline__ void mma16(float* c, const uint32_t* a, uint32_t b0, uint32_t b1) {
    asm volatile(
        "mma.sync.aligned.m16n8k16.row.col.f32.f16.f16.f32 "
        "{%0,%1,%2,%3}, {%4,%5,%6,%7}, {%8,%9}, {%0,%1,%2,%3};"
        : "+f"(c[0]), "+f"(c[1]), "+f"(c[2]), "+f"(c[3])
        : "r"(a[0]), "r"(a[1]), "r"(a[2]), "r"(a[3]), "r"(b0), "r"(b1));
}

__device__ __forceinline__ void split2(float vx, float vy, uint32_t& hi, uint32_t& lo) {
    __half hx = __float2half_rn(vx), hy = __float2half_rn(vy);
    __half lx = __float2half_rn(vx - __half2float(hx));
    __half ly = __float2half_rn(vy - __half2float(hy));
    __half2 h2 = __halves2half2(hx, hy);
    __half2 l2 = __halves2half2(lx, ly);
    hi = *reinterpret_cast<uint32_t*>(&h2);
    lo = *reinterpret_cast<uint32_t*>(&l2);
}

// ---------------- prep kernels ----------------
__global__ void k_zero() {
    int i = blockIdx.x * blockDim.x + threadIdx.x;
    if (i < 4 * NN) ((int*)g_cnt)[i] = 0;
}

// out-degree histogram (needed by GEMM<0> epilogue path, stream s2)
__global__ void k_histO(const int* __restrict__ si, const int* __restrict__ sb) {
    int e = blockIdx.x * blockDim.x + threadIdx.x;
    if (e < EE) {
        atomicAdd(&g_cnt[0][si[e]], 1);
        atomicAdd(&g_cnt[2][sb[e]], 1);
    }
}
// in-degree histogram (needed by CSR build, stream 0)
__global__ void k_histI(const int* __restrict__ di, const int* __restrict__ db) {
    int e = blockIdx.x * blockDim.x + threadIdx.x;
    if (e < EE) {
        atomicAdd(&g_cnt[1][di[e]], 1);
        atomicAdd(&g_cnt[3][db[e]], 1);
    }
}

__global__ void k_normO() {
    int i = blockIdx.x * blockDim.x + threadIdx.x;
    if (i < NN) {
        int c0 = max(g_cnt[0][i], 1), c2 = max(g_cnt[2][i], 1);
        g_norm[0][i] = rsqrtf((float)c0);
        g_norm[2][i] = rsqrtf((float)c2);
    }
}
__global__ void k_normI() {
    int i = blockIdx.x * blockDim.x + threadIdx.x;
    if (i < NN) {
        int c1 = max(g_cnt[1][i], 1), c3 = max(g_cnt[3][i], 1);
        g_norm[1][i] = rsqrtf((float)c1);
        g_norm[3][i] = rsqrtf((float)c3);
    }
}

// Pack W into per-lane m16n8k16 f16 B-fragment order + fp16 split.
// Word layout: idx = (ks*16 + nt)*64 + lane*2 + reg
//   n = nt*8 + (lane>>2); k = ks*16 + (lane&3)*2 + reg*8; halves = {k, k+1}
__global__ void k_prepW(const float* __restrict__ W1i, const float* __restrict__ W1b,
                        const float* __restrict__ W2) {
    int i = blockIdx.x * blockDim.x + threadIdx.x;
    if (i >= 3 * 8192) return;
    int m = i / 8192;
    int idx = i & 8191;
    int frag = idx >> 6;            // ks*16 + nt
    int ks = frag >> 4, nt = frag & 15;
    int rem = idx & 63;
    int lane = rem >> 1, reg = rem & 1;
    int n = nt * 8 + (lane >> 2);
    int k = ks * 16 + (lane & 3) * 2 + reg * 8;
    const float* W = (m == 0) ? W1i : (m == 1) ? W1b : W2;
    float v0 = W[k * FD + n];
    float v1 = W[(k + 1) * FD + n];
    uint32_t hi, lo;
    split2(v0, v1, hi, lo);
    g_Wp[2 * m][idx] = hi;
    g_Wp[2 * m + 1][idx] = lo;
}

__global__ void k_scanA() {
    int rel = blockIdx.y;
    const int* cnt = g_cnt[1 + 2 * rel];
    int base = blockIdx.x * CHUNK;
    int sum = 0;
    for (int i = threadIdx.x; i < CHUNK; i += 256) {
        int gi = base + i;
        sum += (gi < NN) ? cnt[gi] : 0;
    }
    __shared__ int sh[8];
    for (int o = 16; o; o >>= 1) sum += __shfl_down_sync(0xFFFFFFFFu, sum, o);
    if ((threadIdx.x & 31) == 0) sh[threadIdx.x >> 5] = sum;
    __syncthreads();
    if (threadIdx.x == 0) {
        int s = 0;
        for (int w = 0; w < 8; w++) s += sh[w];
        g_csums[rel][blockIdx.x] = s;
    }
}

__global__ void k_scanB() {
    int rel = blockIdx.x;
    __shared__ int sh[NCH];
    if (threadIdx.x < NCH) sh[threadIdx.x] = g_csums[rel][threadIdx.x];
    __syncthreads();
    if (threadIdx.x == 0) {
        int acc = 0;
        for (int i = 0; i < NCH; i++) { int v = sh[i]; sh[i] = acc; acc += v; }
    }
    __syncthreads();
    if (threadIdx.x < NCH) g_csums[rel][threadIdx.x] = sh[threadIdx.x];
}

// per-chunk scan -> rowptr AND write-cursor copy (saves a later pass + csrfill reads)
__global__ void k_scanC() {
    int rel = blockIdx.y;
    const int* cnt = g_cnt[1 + 2 * rel];
    int* rp = g_rowptr[rel];
    int gi = blockIdx.x * CHUNK + threadIdx.x;
    int v = (gi < NN) ? cnt[gi] : 0;
    __shared__ int sh[CHUNK];
    sh[threadIdx.x] = v;
    __syncthreads();
    int val = v;
    for (int off = 1; off < CHUNK; off <<= 1) {
        int t2 = (threadIdx.x >= off) ? sh[threadIdx.x - off] : 0;
        __syncthreads();
        val += t2;
        sh[threadIdx.x] = val;
        __syncthreads();
    }
    int offc = g_csums[rel][blockIdx.x];
    if (gi < NN) {
        int ex = offc + val - v;
        rp[gi] = ex;
        g_cur[rel][gi] = ex;
    }
    if (gi == NN - 1) rp[NN] = offc + val;
}

__global__ void k_csrfill(const int* __restrict__ si, const int* __restrict__ di,
                          const int* __restrict__ sb, const int* __restrict__ db) {
    int e = blockIdx.x * blockDim.x + threadIdx.x;
    if (e < EE) {
        int p = atomicAdd(&g_cur[0][di[e]], 1);
        g_col[0][p] = si[e];
        p = atomicAdd(&g_cur[1][db[e]], 1);
        g_col[1][p] = sb[e];
    }
}

// ---------------- split-fp16 mma GEMM ----------------
// Y[NN,128] = X[NN,128] @ W[128,128], split-fp16 (hh + hl + lh), fp16 packed output.
// One CTA = 128x128 tile, 8 warps: warp w -> rows w*16..w*16+15, all 128 cols.
// MODE 0: X = x param, blockIdx.y selects W1i->g_H1h*nout_i or W1b->g_H1Bh*nout_b.
// MODE 1: X = g_H, W2 -> g_H1h, no scale. boff = 128-row block offset.
#define XS_STRIDE 132

template <int MODE>
__global__ __launch_bounds__(256, 2) void k_gemm_mma(const float* __restrict__ Xext, int boff) {
    extern __shared__ float xs[];   // [128][XS_STRIDE]
    const float* __restrict__ X = (MODE == 0) ? Xext : g_H;
    const int t = threadIdx.x, wid = t >> 5, lane = t & 31;
    const int bm = (blockIdx.x + boff) * 128;

    // stage X tile (zero-padded)
    for (int i = t; i < 128 * 32; i += 256) {
        int r = i >> 5, c4 = (i & 31) * 4;
        float4 v = make_float4(0.f, 0.f, 0.f, 0.f);
        if (bm + r < NN) v = *(const float4*)(X + (size_t)(bm + r) * FD + c4);
        *(float4*)&xs[r * XS_STRIDE + c4] = v;
    }
    __syncthreads();

    const uint32_t* __restrict__ Wh = g_Wp[(MODE == 0) ? 2 * blockIdx.y : 4];
    const uint32_t* __restrict__ Wl = g_Wp[(MODE == 0) ? 2 * blockIdx.y + 1 : 5];

    float acc[16][4];
#pragma unroll
    for (int nt = 0; nt < 16; nt++)
#pragma unroll
        for (int j = 0; j < 4; j++) acc[nt][j] = 0.f;

    const int r0 = wid * 16 + (lane >> 2);   // local row of a0/a2
    const int c0 = (lane & 3) * 2;

#pragma unroll
    for (int ks = 0; ks < 8; ks++) {
        const int k0 = ks * 16;
        float2 v00 = *(const float2*)&xs[r0 * XS_STRIDE + k0 + c0];
        float2 v10 = *(const float2*)&xs[(r0 + 8) * XS_STRIDE + k0 + c0];
        float2 v01 = *(const float2*)&xs[r0 * XS_STRIDE + k0 + 8 + c0];
        float2 v11 = *(const float2*)&xs[(r0 + 8) * XS_STRIDE + k0 + 8 + c0];
        uint32_t ah[4], al[4];
        split2(v00.x, v00.y, ah[0], al[0]);
        split2(v10.x, v10.y, ah[1], al[1]);
        split2(v01.x, v01.y, ah[2], al[2]);
        split2(v11.x, v11.y, ah[3], al[3]);

        const uint2* wh = (const uint2*)(Wh + ks * 1024) + lane;
        const uint2* wl = (const uint2*)(Wl + ks * 1024) + lane;
#pragma unroll
        for (int nt = 0; nt < 16; nt++) {
            uint2 bh = wh[nt * 32];
            uint2 bl = wl[nt * 32];
            mma16(acc[nt], ah, bh.x, bh.y);   // hh
            mma16(acc[nt], al, bh.x, bh.y);   // lh
            mma16(acc[nt], ah, bl.x, bl.y);   // hl
        }
    }

    // epilogue: pack to half2
    const int m0 = bm + r0;
    const int m1 = m0 + 8;
    float s0 = 1.f, s1 = 1.f;
    __half2* O = g_H1h;
    if (MODE == 0) {
        int which = blockIdx.y ? 2 : 0;
        if (m0 < NN) s0 = g_norm[which][m0];
        if (m1 < NN) s1 = g_norm[which][m1];
        if (blockIdx.y) O = g_H1Bh;
    }
    const int hc = lane & 3;   // half2 col offset within n-tile
#pragma unroll
    for (int nt = 0; nt < 16; nt++) {
        int hcol = nt * 4 + hc;
        if (m0 < NN) O[(size_t)m0 * 64 + hcol] = __floats2half2_rn(acc[nt][0] * s0, acc[nt][1] * s0);
        if (m1 < NN) O[(size_t)m1 * 64 + hcol] = __floats2half2_rn(acc[nt][2] * s1, acc[nt][3] * s1);
    }
}

// ---------------- SpMM: 64 lanes (half2 features) x 4 nodes per block ----------------
__device__ __forceinline__ float2 gather_h(const __half2* __restrict__ H,
                                           const int* __restrict__ col,
                                           int e, int e1, int lane) {
    float a0 = 0.f, a1 = 0.f;
    for (; e + 4 <= e1; e += 4) {
        int s0 = col[e], s1 = col[e + 1], s2 = col[e + 2], s3 = col[e + 3];
        float2 f0 = __half22float2(H[(size_t)s0 * 64 + lane]);
        float2 f1 = __half22float2(H[(size_t)s1 * 64 + lane]);
        float2 f2 = __half22float2(H[(size_t)s2 * 64 + lane]);
        float2 f3 = __half22float2(H[(size_t)s3 * 64 + lane]);
        a0 += (f0.x + f1.x) + (f2.x + f3.x);
        a1 += (f0.y + f1.y) + (f2.y + f3.y);
    }
    for (; e < e1; e++) {
        float2 f = __half22float2(H[(size_t)col[e] * 64 + lane]);
        a0 += f.x;
        a1 += f.y;
    }
    return make_float2(a0, a1);
}

__global__ void k_spmm1(const float* __restrict__ b1i, const float* __restrict__ b1b, int voff) {
    int v = voff + blockIdx.x * 4 + threadIdx.y;
    if (v >= NN) return;
    int lane = threadIdx.x;
    float2 ai = gather_h(g_H1h,  g_col[0], g_rowptr[0][v], g_rowptr[0][v + 1], lane);
    float2 ab = gather_h(g_H1Bh, g_col[1], g_rowptr[1][v], g_rowptr[1][v + 1], lane);
    float n1 = g_norm[1][v], n3 = g_norm[3][v], n0 = g_norm[0][v];
    float h0 = fmaxf(ai.x * n1 + b1i[2 * lane], 0.f) + fmaxf(ab.x * n3 + b1b[2 * lane], 0.f);
    float h1 = fmaxf(ai.y * n1 + b1i[2 * lane + 1], 0.f) + fmaxf(ab.y * n3 + b1b[2 * lane + 1], 0.f);
    *(float2*)&g_H[(size_t)v * 128 + 2 * lane] = make_float2(h0 * n0, h1 * n0);
}

__global__ void k_spmm2(const float* __restrict__ b2, float* __restrict__ out) {
    int v = blockIdx.x * 4 + threadIdx.y;
    if (v >= NN) return;
    int lane = threadIdx.x;
    float2 a = gather_h(g_H1h, g_col[0], g_rowptr[0][v], g_rowptr[0][v + 1], lane);
    float n1 = g_norm[1][v];
    *(float2*)&out[(size_t)v * 128 + 2 * lane] =
        make_float2(a.x * n1 + b2[2 * lane], a.y * n1 + b2[2 * lane + 1]);
}

// ---------------- launch ----------------
extern "C" void kernel_launch(void* const* d_in, const int* in_sizes, int n_in,
                              void* d_out, int out_size) {
    (void)in_sizes; (void)n_in; (void)out_size;
    const float* x    = (const float*)d_in[0];
    const int*   si   = (const int*)d_in[1];
    const int*   di   = (const int*)d_in[2];
    const int*   sb   = (const int*)d_in[3];
    const int*   db   = (const int*)d_in[4];
    const float* W1i  = (const float*)d_in[5];
    const float* b1i  = (const float*)d_in[6];
    const float* W1b  = (const float*)d_in[7];
    const float* b1b  = (const float*)d_in[8];
    const float* W2   = (const float*)d_in[9];
    const float* b2   = (const float*)d_in[10];
    float* out = (float*)d_out;

    const int XS_BYTES = 128 * XS_STRIDE * sizeof(float);   // 67584

    static cudaStream_t s2 = nullptr;
    static cudaEvent_t evZ = nullptr, evA = nullptr, ev1 = nullptr, ev2 = nullptr, evG = nullptr;
    static int init_done = 0;
    if (!init_done) {   // first (uncaptured) correctness call only
        cudaFuncSetAttribute(k_gemm_mma<0>, cudaFuncAttributeMaxDynamicSharedMemorySize, XS_BYTES);
        cudaFuncSetAttribute(k_gemm_mma<1>, cudaFuncAttributeMaxDynamicSharedMemorySize, XS_BYTES);
        cudaStreamCreateWithFlags(&s2, cudaStreamNonBlocking);
        cudaEventCreateWithFlags(&evZ, cudaEventDisableTiming);
        cudaEventCreateWithFlags(&evA, cudaEventDisableTiming);
        cudaEventCreateWithFlags(&ev1, cudaEventDisableTiming);
        cudaEventCreateWithFlags(&ev2, cudaEventDisableTiming);
        cudaEventCreateWithFlags(&evG, cudaEventDisableTiming);
        init_done = 1;
    }

    const int gblk = (NN + 127) / 128;   // 782
    const dim3 sblk(64, 4);

    // ---- fork after zero ----
    k_zero<<<(4 * NN + 255) / 256, 256>>>();
    cudaEventRecord(evZ, 0);
    cudaStreamWaitEvent(s2, evZ, 0);

    // s2: transform branch (out-degrees + weights + GEMM<0>)
    k_prepW<<<(3 * 8192 + 255) / 256, 256, 0, s2>>>(W1i, W1b, W2);
    k_histO<<<(EE + 255) / 256, 256, 0, s2>>>(si, sb);
    k_normO<<<(NN + 255) / 256, 256, 0, s2>>>();
    k_gemm_mma<0><<<dim3(gblk, 2), 256, XS_BYTES, s2>>>(x, 0);   // g_H1h, g_H1Bh
    cudaEventRecord(evA, s2);

    // s0: graph branch (in-degrees + CSR)
    k_histI<<<(EE + 255) / 256, 256>>>(di, db);
    k_normI<<<(NN + 255) / 256, 256>>>();
    {
        dim3 ga(NCH, 2);
        k_scanA<<<ga, 256>>>();
        k_scanB<<<2, 128>>>();
        k_scanC<<<ga, CHUNK>>>();
    }
    k_csrfill<<<(EE + 255) / 256, 256>>>(si, di, sb, db);

    // join transform branch, then pipelined spmm1 / gemm<1>
    cudaStreamWaitEvent(0, evA, 0);

    k_spmm1<<<NODES_C0 / 4, sblk>>>(b1i, b1b, 0);                 // nodes [0, 50048)
    cudaEventRecord(ev1, 0);
    k_spmm1<<<(NN - NODES_C0 + 3) / 4, sblk>>>(b1i, b1b, NODES_C0); // nodes [50048, NN)
    cudaEventRecord(ev2, 0);

    cudaStreamWaitEvent(s2, ev1, 0);
    k_gemm_mma<1><<<dim3(GBLK_C0, 1), 256, XS_BYTES, s2>>>(nullptr, 0);
    cudaStreamWaitEvent(s2, ev2, 0);
    k_gemm_mma<1><<<dim3(gblk - GBLK_C0, 1), 256, XS_BYTES, s2>>>(nullptr, GBLK_C0);
    cudaEventRecord(evG, s2);

    cudaStreamWaitEvent(0, evG, 0);
    k_spmm2<<<(NN + 3) / 4, sblk>>>(b2, out);
}

// round 7
// speedup vs baseline: 1.0796x; 1.0796x over previous
#include <cuda_runtime.h>
#include <cuda_fp16.h>
#include <cstdint>

#define NN 100000
#define EE 1600000
#define FD 128
#define CHUNK 1024
#define NCH ((NN + CHUNK - 1) / CHUNK)   // 98

// ---------------- device scratch (static, no allocation) ----------------
__device__ int      g_cnt[4][NN];          // 0: out_i, 1: in_i, 2: out_b, 3: in_b
__device__ float    g_norm[4][NN];         // rsqrt(max(cnt,1))
__device__ int      g_rowptr[2][NN + 1];   // CSR by dst: 0=interacts, 1=behave
__device__ int      g_cur[2][NN];          // write cursors (init = rowptr in scanC)
__device__ int      g_col[2][EE];          // src indices per CSR slot
__device__ int      g_csums[2][NCH];
__device__ __half2  g_H1h[NN * 64];        // (x@W1_i)*nout_i (fp16, gathered); reused for H@W2
__device__ __half2  g_H1Bh[NN * 64];       // (x@W1_b)*nout_b (fp16, gathered)
__device__ __half2  g_Hh[NN * 64];         // conv1 output fp16, pre-scaled by nout_i
// W packed into mma.sync m16n8k16 f16 B-fragment order (half2 words), fp16-split:
// [0/1]: W1i hi/lo, [2/3]: W1b hi/lo, [4/5]: W2 hi/lo. 8192 u32 each.
__device__ uint32_t g_Wp[6][FD * FD / 2];

// ---------------- helpers ----------------
__device__ __forceinline__ void mma16(float* c, const uint32_t* a, uint32_t b0, uint32_t b1) {
    asm volatile(
        "mma.sync.aligned.m16n8k16.row.col.f32.f16.f16.f32 "
        "{%0,%1,%2,%3}, {%4,%5,%6,%7}, {%8,%9}, {%0,%1,%2,%3};"
        : "+f"(c[0]), "+f"(c[1]), "+f"(c[2]), "+f"(c[3])
        : "r"(a[0]), "r"(a[1]), "r"(a[2]), "r"(a[3]), "r"(b0), "r"(b1));
}

__device__ __forceinline__ void split2(float vx, float vy, uint32_t& hi, uint32_t& lo) {
    __half hx = __float2half_rn(vx), hy = __float2half_rn(vy);
    __half lx = __float2half_rn(vx - __half2float(hx));
    __half ly = __float2half_rn(vy - __half2float(hy));
    __half2 h2 = __halves2half2(hx, hy);
    __half2 l2 = __halves2half2(lx, ly);
    hi = *reinterpret_cast<uint32_t*>(&h2);
    lo = *reinterpret_cast<uint32_t*>(&l2);
}

// ---------------- prep kernels ----------------
__global__ void k_zero() {
    int i = blockIdx.x * blockDim.x + threadIdx.x;
    if (i < 4 * NN) ((int*)g_cnt)[i] = 0;
}

__global__ void k_hist(const int* __restrict__ si, const int* __restrict__ di,
                       const int* __restrict__ sb, const int* __restrict__ db) {
    int e = blockIdx.x * blockDim.x + threadIdx.x;
    if (e < EE) {
        atomicAdd(&g_cnt[0][si[e]], 1);
        atomicAdd(&g_cnt[1][di[e]], 1);
        atomicAdd(&g_cnt[2][sb[e]], 1);
        atomicAdd(&g_cnt[3][db[e]], 1);
    }
}

__global__ void k_norm() {
    int i = blockIdx.x * blockDim.x + threadIdx.x;
    if (i < NN) {
#pragma unroll
        for (int r = 0; r < 4; r++) {
            int c = g_cnt[r][i];
            if (c < 1) c = 1;
            g_norm[r][i] = rsqrtf((float)c);
        }
    }
}

// Pack W into per-lane m16n8k16 f16 B-fragment order + fp16 split.
// Word layout: idx = (ks*16 + nt)*64 + lane*2 + reg
//   n = nt*8 + (lane>>2); k = ks*16 + (lane&3)*2 + reg*8; halves = {k, k+1}
__global__ void k_prepW(const float* __restrict__ W1i, const float* __restrict__ W1b,
                        const float* __restrict__ W2) {
    int i = blockIdx.x * blockDim.x + threadIdx.x;
    if (i >= 3 * 8192) return;
    int m = i / 8192;
    int idx = i & 8191;
    int frag = idx >> 6;            // ks*16 + nt
    int ks = frag >> 4, nt = frag & 15;
    int rem = idx & 63;
    int lane = rem >> 1, reg = rem & 1;
    int n = nt * 8 + (lane >> 2);
    int k = ks * 16 + (lane & 3) * 2 + reg * 8;
    const float* W = (m == 0) ? W1i : (m == 1) ? W1b : W2;
    float v0 = W[k * FD + n];
    float v1 = W[(k + 1) * FD + n];
    uint32_t hi, lo;
    split2(v0, v1, hi, lo);
    g_Wp[2 * m][idx] = hi;
    g_Wp[2 * m + 1][idx] = lo;
}

__global__ void k_scanA() {
    int rel = blockIdx.y;
    const int* cnt = g_cnt[1 + 2 * rel];
    int base = blockIdx.x * CHUNK;
    int sum = 0;
    for (int i = threadIdx.x; i < CHUNK; i += 256) {
        int gi = base + i;
        sum += (gi < NN) ? cnt[gi] : 0;
    }
    __shared__ int sh[8];
    for (int o = 16; o; o >>= 1) sum += __shfl_down_sync(0xFFFFFFFFu, sum, o);
    if ((threadIdx.x & 31) == 0) sh[threadIdx.x >> 5] = sum;
    __syncthreads();
    if (threadIdx.x == 0) {
        int s = 0;
        for (int w = 0; w < 8; w++) s += sh[w];
        g_csums[rel][blockIdx.x] = s;
    }
}

__global__ void k_scanB() {
    int rel = blockIdx.x;
    __shared__ int sh[NCH];
    if (threadIdx.x < NCH) sh[threadIdx.x] = g_csums[rel][threadIdx.x];
    __syncthreads();
    if (threadIdx.x == 0) {
        int acc = 0;
        for (int i = 0; i < NCH; i++) { int v = sh[i]; sh[i] = acc; acc += v; }
    }
    __syncthreads();
    if (threadIdx.x < NCH) g_csums[rel][threadIdx.x] = sh[threadIdx.x];
}

// per-chunk scan -> rowptr AND write-cursor copy
__global__ void k_scanC() {
    int rel = blockIdx.y;
    const int* cnt = g_cnt[1 + 2 * rel];
    int* rp = g_rowptr[rel];
    int gi = blockIdx.x * CHUNK + threadIdx.x;
    int v = (gi < NN) ? cnt[gi] : 0;
    __shared__ int sh[CHUNK];
    sh[threadIdx.x] = v;
    __syncthreads();
    int val = v;
    for (int off = 1; off < CHUNK; off <<= 1) {
        int t2 = (threadIdx.x >= off) ? sh[threadIdx.x - off] : 0;
        __syncthreads();
        val += t2;
        sh[threadIdx.x] = val;
        __syncthreads();
    }
    int offc = g_csums[rel][blockIdx.x];
    if (gi < NN) {
        int ex = offc + val - v;
        rp[gi] = ex;
        g_cur[rel][gi] = ex;
    }
    if (gi == NN - 1) rp[NN] = offc + val;
}

__global__ void k_csrfill(const int* __restrict__ si, const int* __restrict__ di,
                          const int* __restrict__ sb, const int* __restrict__ db) {
    int e = blockIdx.x * blockDim.x + threadIdx.x;
    if (e < EE) {
        int p = atomicAdd(&g_cur[0][di[e]], 1);
        g_col[0][p] = si[e];
        p = atomicAdd(&g_cur[1][db[e]], 1);
        g_col[1][p] = sb[e];
    }
}

// ---------------- GEMM 0: fp32 x -> split-fp16 (hh + lh + hl), dual output ----------------
// One CTA = 128x128 tile, 8 warps. blockIdx.y: 0 -> W1i->g_H1h*nout_i, 1 -> W1b->g_H1Bh*nout_b.
#define XS_STRIDE 132

__global__ __launch_bounds__(256, 2) void k_gemm0(const float* __restrict__ X) {
    extern __shared__ float xs[];   // [128][XS_STRIDE]
    const int t = threadIdx.x, wid = t >> 5, lane = t & 31;
    const int bm = blockIdx.x * 128;

    for (int i = t; i < 128 * 32; i += 256) {
        int r = i >> 5, c4 = (i & 31) * 4;
        float4 v = make_float4(0.f, 0.f, 0.f, 0.f);
        if (bm + r < NN) v = *(const float4*)(X + (size_t)(bm + r) * FD + c4);
        *(float4*)&xs[r * XS_STRIDE + c4] = v;
    }
    __syncthreads();

    const uint32_t* __restrict__ Wh = g_Wp[2 * blockIdx.y];
    const uint32_t* __restrict__ Wl = g_Wp[2 * blockIdx.y + 1];

    float acc[16][4];
#pragma unroll
    for (int nt = 0; nt < 16; nt++)
#pragma unroll
        for (int j = 0; j < 4; j++) acc[nt][j] = 0.f;

    const int r0 = wid * 16 + (lane >> 2);
    const int c0 = (lane & 3) * 2;

#pragma unroll
    for (int ks = 0; ks < 8; ks++) {
        const int k0 = ks * 16;
        float2 v00 = *(const float2*)&xs[r0 * XS_STRIDE + k0 + c0];
        float2 v10 = *(const float2*)&xs[(r0 + 8) * XS_STRIDE + k0 + c0];
        float2 v01 = *(const float2*)&xs[r0 * XS_STRIDE + k0 + 8 + c0];
        float2 v11 = *(const float2*)&xs[(r0 + 8) * XS_STRIDE + k0 + 8 + c0];
        uint32_t ah[4], al[4];
        split2(v00.x, v00.y, ah[0], al[0]);
        split2(v10.x, v10.y, ah[1], al[1]);
        split2(v01.x, v01.y, ah[2], al[2]);
        split2(v11.x, v11.y, ah[3], al[3]);

        const uint2* wh = (const uint2*)(Wh + ks * 1024) + lane;
        const uint2* wl = (const uint2*)(Wl + ks * 1024) + lane;
#pragma unroll
        for (int nt = 0; nt < 16; nt++) {
            uint2 bh = wh[nt * 32];
            uint2 bl = wl[nt * 32];
            mma16(acc[nt], ah, bh.x, bh.y);   // hh
            mma16(acc[nt], al, bh.x, bh.y);   // lh
            mma16(acc[nt], ah, bl.x, bl.y);   // hl
        }
    }

    const int m0 = bm + r0;
    const int m1 = m0 + 8;
    const int which = blockIdx.y ? 2 : 0;
    float s0 = (m0 < NN) ? g_norm[which][m0] : 1.f;
    float s1 = (m1 < NN) ? g_norm[which][m1] : 1.f;
    __half2* O = blockIdx.y ? g_H1Bh : g_H1h;
    const int hc = lane & 3;
#pragma unroll
    for (int nt = 0; nt < 16; nt++) {
        int hcol = nt * 4 + hc;
        if (m0 < NN) O[(size_t)m0 * 64 + hcol] = __floats2half2_rn(acc[nt][0] * s0, acc[nt][1] * s0);
        if (m1 < NN) O[(size_t)m1 * 64 + hcol] = __floats2half2_rn(acc[nt][2] * s1, acc[nt][3] * s1);
    }
}

// ---------------- GEMM 1: fp16 g_Hh @ W2 -> g_H1h (A exact fp16: 2 passes) ----------------
#define XH_STRIDE 68

__global__ __launch_bounds__(256, 2) void k_gemm1() {
    extern __shared__ uint32_t xh[];   // [128][XH_STRIDE] half2 words
    const int t = threadIdx.x, wid = t >> 5, lane = t & 31;
    const int bm = blockIdx.x * 128;
    const uint32_t* __restrict__ Hh = (const uint32_t*)g_Hh;

    for (int i = t; i < 128 * 16; i += 256) {
        int r = i >> 4, c4 = (i & 15) * 4;
        uint4 v = make_uint4(0u, 0u, 0u, 0u);
        if (bm + r < NN) v = *(const uint4*)(Hh + (size_t)(bm + r) * 64 + c4);
        *(uint4*)&xh[r * XH_STRIDE + c4] = v;
    }
    __syncthreads();

    const uint32_t* __restrict__ Wh = g_Wp[4];
    const uint32_t* __restrict__ Wl = g_Wp[5];

    float acc[16][4];
#pragma unroll
    for (int nt = 0; nt < 16; nt++)
#pragma unroll
        for (int j = 0; j < 4; j++) acc[nt][j] = 0.f;

    const int r0 = wid * 16 + (lane >> 2);
    const int cw = lane & 3;   // half2 word within k-group

#pragma unroll
    for (int ks = 0; ks < 8; ks++) {
        uint32_t ah[4];
        ah[0] = xh[r0 * XH_STRIDE + ks * 8 + cw];
        ah[1] = xh[(r0 + 8) * XH_STRIDE + ks * 8 + cw];
        ah[2] = xh[r0 * XH_STRIDE + ks * 8 + 4 + cw];
        ah[3] = xh[(r0 + 8) * XH_STRIDE + ks * 8 + 4 + cw];

        const uint2* wh = (const uint2*)(Wh + ks * 1024) + lane;
        const uint2* wl = (const uint2*)(Wl + ks * 1024) + lane;
#pragma unroll
        for (int nt = 0; nt < 16; nt++) {
            uint2 bh = wh[nt * 32];
            uint2 bl = wl[nt * 32];
            mma16(acc[nt], ah, bh.x, bh.y);   // A * W_hi
            mma16(acc[nt], ah, bl.x, bl.y);   // A * W_lo
        }
    }

    const int m0 = bm + r0;
    const int m1 = m0 + 8;
    const int hc = lane & 3;
#pragma unroll
    for (int nt = 0; nt < 16; nt++) {
        int hcol = nt * 4 + hc;
        if (m0 < NN) g_H1h[(size_t)m0 * 64 + hcol] = __floats2half2_rn(acc[nt][0], acc[nt][1]);
        if (m1 < NN) g_H1h[(size_t)m1 * 64 + hcol] = __floats2half2_rn(acc[nt][2], acc[nt][3]);
    }
}

// ---------------- SpMM: 64 lanes (half2 features) x 4 nodes per block ----------------
__device__ __forceinline__ float2 gather_h(const __half2* __restrict__ H,
                                           const int* __restrict__ col,
                                           int e, int e1, int lane) {
    float a0 = 0.f, a1 = 0.f;
    for (; e + 4 <= e1; e += 4) {
        int s0 = col[e], s1 = col[e + 1], s2 = col[e + 2], s3 = col[e + 3];
        float2 f0 = __half22float2(H[(size_t)s0 * 64 + lane]);
        float2 f1 = __half22float2(H[(size_t)s1 * 64 + lane]);
        float2 f2 = __half22float2(H[(size_t)s2 * 64 + lane]);
        float2 f3 = __half22float2(H[(size_t)s3 * 64 + lane]);
        a0 += (f0.x + f1.x) + (f2.x + f3.x);
        a1 += (f0.y + f1.y) + (f2.y + f3.y);
    }
    for (; e < e1; e++) {
        float2 f = __half22float2(H[(size_t)col[e] * 64 + lane]);
        a0 += f.x;
        a1 += f.y;
    }
    return make_float2(a0, a1);
}

__global__ void k_spmm1(const float* __restrict__ b1i, const float* __restrict__ b1b) {
    int v = blockIdx.x * 4 + threadIdx.y;
    if (v >= NN) return;
    int lane = threadIdx.x;
    float2 ai = gather_h(g_H1h,  g_col[0], g_rowptr[0][v], g_rowptr[0][v + 1], lane);
    float2 ab = gather_h(g_H1Bh, g_col[1], g_rowptr[1][v], g_rowptr[1][v + 1], lane);
    float n1 = g_norm[1][v], n3 = g_norm[3][v], n0 = g_norm[0][v];
    float h0 = fmaxf(ai.x * n1 + b1i[2 * lane], 0.f) + fmaxf(ab.x * n3 + b1b[2 * lane], 0.f);
    float h1 = fmaxf(ai.y * n1 + b1i[2 * lane + 1], 0.f) + fmaxf(ab.y * n3 + b1b[2 * lane + 1], 0.f);
    g_Hh[(size_t)v * 64 + lane] = __floats2half2_rn(h0 * n0, h1 * n0);
}

__global__ void k_spmm2(const float* __restrict__ b2, float* __restrict__ out) {
    int v = blockIdx.x * 4 + threadIdx.y;
    if (v >= NN) return;
    int lane = threadIdx.x;
    float2 a = gather_h(g_H1h, g_col[0], g_rowptr[0][v], g_rowptr[0][v + 1], lane);
    float n1 = g_norm[1][v];
    *(float2*)&out[(size_t)v * 128 + 2 * lane] =
        make_float2(a.x * n1 + b2[2 * lane], a.y * n1 + b2[2 * lane + 1]);
}

// ---------------- launch ----------------
extern "C" void kernel_launch(void* const* d_in, const int* in_sizes, int n_in,
                              void* d_out, int out_size) {
    (void)in_sizes; (void)n_in; (void)out_size;
    const float* x    = (const float*)d_in[0];
    const int*   si   = (const int*)d_in[1];
    const int*   di   = (const int*)d_in[2];
    const int*   sb   = (const int*)d_in[3];
    const int*   db   = (const int*)d_in[4];
    const float* W1i  = (const float*)d_in[5];
    const float* b1i  = (const float*)d_in[6];
    const float* W1b  = (const float*)d_in[7];
    const float* b1b  = (const float*)d_in[8];
    const float* W2   = (const float*)d_in[9];
    const float* b2   = (const float*)d_in[10];
    float* out = (float*)d_out;

    const int XS_BYTES = 128 * XS_STRIDE * sizeof(float);     // 67584
    const int XH_BYTES = 128 * XH_STRIDE * sizeof(uint32_t);  // 34816

    static cudaStream_t s2 = nullptr;
    static cudaEvent_t evF = nullptr, evG = nullptr;
    static int init_done = 0;
    if (!init_done) {   // first (uncaptured) correctness call only
        cudaFuncSetAttribute(k_gemm0, cudaFuncAttributeMaxDynamicSharedMemorySize, XS_BYTES);
        cudaStreamCreateWithFlags(&s2, cudaStreamNonBlocking);
        cudaEventCreateWithFlags(&evF, cudaEventDisableTiming);
        cudaEventCreateWithFlags(&evG, cudaEventDisableTiming);
        init_done = 1;
    }

    const int gblk = (NN + 127) / 128;   // 782
    const dim3 sblk(64, 4);
    const int sgrid = (NN + 3) / 4;      // 25000

    // common prefix (stream 0)
    k_zero<<<(4 * NN + 255) / 256, 256>>>();
    k_hist<<<(EE + 255) / 256, 256>>>(si, di, sb, db);
    k_prepW<<<(3 * 8192 + 255) / 256, 256>>>(W1i, W1b, W2);
    k_norm<<<(NN + 255) / 256, 256>>>();

    // fork: GEMM0 (tensor-bound) on s2, CSR build (memory-bound) on stream 0
    cudaEventRecord(evF, 0);
    cudaStreamWaitEvent(s2, evF, 0);
    k_gemm0<<<dim3(gblk, 2), 256, XS_BYTES, s2>>>(x);   // g_H1h, g_H1Bh

    {
        dim3 ga(NCH, 2);
        k_scanA<<<ga, 256>>>();
        k_scanB<<<2, 128>>>();
        k_scanC<<<ga, CHUNK>>>();
    }
    k_csrfill<<<(EE + 255) / 256, 256>>>(si, di, sb, db);

    // join
    cudaEventRecord(evG, s2);
    cudaStreamWaitEvent(0, evG, 0);

    k_spmm1<<<sgrid, sblk>>>(b1i, b1b);            // g_Hh (fp16)
    k_gemm1<<<gblk, 256, XH_BYTES>>>();            // g_H1h = g_Hh @ W2
    k_spmm2<<<sgrid, sblk>>>(b2, out);
}

// round 8
// speedup vs baseline: 1.3751x; 1.2738x over previous
#include <cuda_runtime.h>
#include <cuda_fp16.h>
#include <cstdint>

#define NN 100000
#define EE 1600000
#define FD 128
#define CHUNK 1024
#define NCH ((NN + CHUNK - 1) / CHUNK)   // 98

// tail pipeline chunking (multiple of 128 and 8)
#define NODES_C0 50048
#define GBLK_C0 (NODES_C0 / 128)         // 391

// ---------------- device scratch (static, no allocation) ----------------
__device__ int      g_cnt[4][NN];          // 0: out_i, 1: in_i, 2: out_b, 3: in_b
__device__ float    g_norm[4][NN];         // rsqrt(max(cnt,1))
__device__ int      g_rowptr[2][NN + 1];   // CSR by dst: 0=interacts, 1=behave
__device__ int      g_cur[2][NN];          // write cursors (init = rowptr in scanC)
__device__ int      g_col[2][EE];          // src indices per CSR slot
__device__ int      g_csums[2][NCH];
__device__ __half2  g_H1h[NN * 64];        // (x@W1_i)*nout_i (fp16, gathered)
__device__ __half2  g_H1Bh[NN * 64];       // (x@W1_b)*nout_b (fp16); reused as agg2 after spmm1
__device__ __half2  g_Hh[NN * 64];         // conv1 output fp16, pre-scaled by nout_i
// W packed into mma.sync m16n8k16 f16 B-fragment order (half2 words), fp16-split:
// [0/1]: W1i hi/lo, [2/3]: W1b hi/lo, [4/5]: W2 hi/lo. 8192 u32 each.
__device__ uint32_t g_Wp[6][FD * FD / 2];

// ---------------- helpers ----------------
__device__ __forceinline__ void mma16(float* c, const uint32_t* a, uint32_t b0, uint32_t b1) {
    asm volatile(
        "mma.sync.aligned.m16n8k16.row.col.f32.f16.f16.f32 "
        "{%0,%1,%2,%3}, {%4,%5,%6,%7}, {%8,%9}, {%0,%1,%2,%3};"
        : "+f"(c[0]), "+f"(c[1]), "+f"(c[2]), "+f"(c[3])
        : "r"(a[0]), "r"(a[1]), "r"(a[2]), "r"(a[3]), "r"(b0), "r"(b1));
}

__device__ __forceinline__ void split2(float vx, float vy, uint32_t& hi, uint32_t& lo) {
    __half hx = __float2half_rn(vx), hy = __float2half_rn(vy);
    __half lx = __float2half_rn(vx - __half2float(hx));
    __half ly = __float2half_rn(vy - __half2float(hy));
    __half2 h2 = __halves2half2(hx, hy);
    __half2 l2 = __halves2half2(lx, ly);
    hi = *reinterpret_cast<uint32_t*>(&h2);
    lo = *reinterpret_cast<uint32_t*>(&l2);
}

// ---------------- prep kernels ----------------
__global__ void k_zero() {
    int i = blockIdx.x * blockDim.x + threadIdx.x;
    if (i < 4 * NN) ((int*)g_cnt)[i] = 0;
}

__global__ void k_hist(const int* __restrict__ si, const int* __restrict__ di,
                       const int* __restrict__ sb, const int* __restrict__ db) {
    int e = blockIdx.x * blockDim.x + threadIdx.x;
    if (e < EE) {
        atomicAdd(&g_cnt[0][si[e]], 1);
        atomicAdd(&g_cnt[1][di[e]], 1);
        atomicAdd(&g_cnt[2][sb[e]], 1);
        atomicAdd(&g_cnt[3][db[e]], 1);
    }
}

__global__ void k_norm() {
    int i = blockIdx.x * blockDim.x + threadIdx.x;
    if (i < NN) {
#pragma unroll
        for (int r = 0; r < 4; r++) {
            int c = g_cnt[r][i];
            if (c < 1) c = 1;
            g_norm[r][i] = rsqrtf((float)c);
        }
    }
}

// Pack W into per-lane m16n8k16 f16 B-fragment order + fp16 split.
__global__ void k_prepW(const float* __restrict__ W1i, const float* __restrict__ W1b,
                        const float* __restrict__ W2) {
    int i = blockIdx.x * blockDim.x + threadIdx.x;
    if (i >= 3 * 8192) return;
    int m = i / 8192;
    int idx = i & 8191;
    int frag = idx >> 6;            // ks*16 + nt
    int ks = frag >> 4, nt = frag & 15;
    int rem = idx & 63;
    int lane = rem >> 1, reg = rem & 1;
    int n = nt * 8 + (lane >> 2);
    int k = ks * 16 + (lane & 3) * 2 + reg * 8;
    const float* W = (m == 0) ? W1i : (m == 1) ? W1b : W2;
    float v0 = W[k * FD + n];
    float v1 = W[(k + 1) * FD + n];
    uint32_t hi, lo;
    split2(v0, v1, hi, lo);
    g_Wp[2 * m][idx] = hi;
    g_Wp[2 * m + 1][idx] = lo;
}

__global__ void k_scanA() {
    int rel = blockIdx.y;
    const int* cnt = g_cnt[1 + 2 * rel];
    int base = blockIdx.x * CHUNK;
    int sum = 0;
    for (int i = threadIdx.x; i < CHUNK; i += 256) {
        int gi = base + i;
        sum += (gi < NN) ? cnt[gi] : 0;
    }
    __shared__ int sh[8];
    for (int o = 16; o; o >>= 1) sum += __shfl_down_sync(0xFFFFFFFFu, sum, o);
    if ((threadIdx.x & 31) == 0) sh[threadIdx.x >> 5] = sum;
    __syncthreads();
    if (threadIdx.x == 0) {
        int s = 0;
        for (int w = 0; w < 8; w++) s += sh[w];
        g_csums[rel][blockIdx.x] = s;
    }
}

__global__ void k_scanB() {
    int rel = blockIdx.x;
    __shared__ int sh[NCH];
    if (threadIdx.x < NCH) sh[threadIdx.x] = g_csums[rel][threadIdx.x];
    __syncthreads();
    if (threadIdx.x == 0) {
        int acc = 0;
        for (int i = 0; i < NCH; i++) { int v = sh[i]; sh[i] = acc; acc += v; }
    }
    __syncthreads();
    if (threadIdx.x < NCH) g_csums[rel][threadIdx.x] = sh[threadIdx.x];
}

__global__ void k_scanC() {
    int rel = blockIdx.y;
    const int* cnt = g_cnt[1 + 2 * rel];
    int* rp = g_rowptr[rel];
    int gi = blockIdx.x * CHUNK + threadIdx.x;
    int v = (gi < NN) ? cnt[gi] : 0;
    __shared__ int sh[CHUNK];
    sh[threadIdx.x] = v;
    __syncthreads();
    int val = v;
    for (int off = 1; off < CHUNK; off <<= 1) {
        int t2 = (threadIdx.x >= off) ? sh[threadIdx.x - off] : 0;
        __syncthreads();
        val += t2;
        sh[threadIdx.x] = val;
        __syncthreads();
    }
    int offc = g_csums[rel][blockIdx.x];
    if (gi < NN) {
        int ex = offc + val - v;
        rp[gi] = ex;
        g_cur[rel][gi] = ex;
    }
    if (gi == NN - 1) rp[NN] = offc + val;
}

__global__ void k_csrfill(const int* __restrict__ si, const int* __restrict__ di,
                          const int* __restrict__ sb, const int* __restrict__ db) {
    int e = blockIdx.x * blockDim.x + threadIdx.x;
    if (e < EE) {
        int p = atomicAdd(&g_cur[0][di[e]], 1);
        g_col[0][p] = si[e];
        p = atomicAdd(&g_cur[1][db[e]], 1);
        g_col[1][p] = sb[e];
    }
}

// ---------------- GEMM 0: fp32 x -> split-fp16 (hh + lh + hl), dual output ----------------
#define XS_STRIDE 132

__global__ __launch_bounds__(256, 2) void k_gemm0(const float* __restrict__ X) {
    extern __shared__ float xs[];   // [128][XS_STRIDE]
    const int t = threadIdx.x, wid = t >> 5, lane = t & 31;
    const int bm = blockIdx.x * 128;

    for (int i = t; i < 128 * 32; i += 256) {
        int r = i >> 5, c4 = (i & 31) * 4;
        float4 v = make_float4(0.f, 0.f, 0.f, 0.f);
        if (bm + r < NN) v = *(const float4*)(X + (size_t)(bm + r) * FD + c4);
        *(float4*)&xs[r * XS_STRIDE + c4] = v;
    }
    __syncthreads();

    const uint32_t* __restrict__ Wh = g_Wp[2 * blockIdx.y];
    const uint32_t* __restrict__ Wl = g_Wp[2 * blockIdx.y + 1];

    float acc[16][4];
#pragma unroll
    for (int nt = 0; nt < 16; nt++)
#pragma unroll
        for (int j = 0; j < 4; j++) acc[nt][j] = 0.f;

    const int r0 = wid * 16 + (lane >> 2);
    const int c0 = (lane & 3) * 2;

#pragma unroll
    for (int ks = 0; ks < 8; ks++) {
        const int k0 = ks * 16;
        float2 v00 = *(const float2*)&xs[r0 * XS_STRIDE + k0 + c0];
        float2 v10 = *(const float2*)&xs[(r0 + 8) * XS_STRIDE + k0 + c0];
        float2 v01 = *(const float2*)&xs[r0 * XS_STRIDE + k0 + 8 + c0];
        float2 v11 = *(const float2*)&xs[(r0 + 8) * XS_STRIDE + k0 + 8 + c0];
        uint32_t ah[4], al[4];
        split2(v00.x, v00.y, ah[0], al[0]);
        split2(v10.x, v10.y, ah[1], al[1]);
        split2(v01.x, v01.y, ah[2], al[2]);
        split2(v11.x, v11.y, ah[3], al[3]);

        const uint2* wh = (const uint2*)(Wh + ks * 1024) + lane;
        const uint2* wl = (const uint2*)(Wl + ks * 1024) + lane;
#pragma unroll
        for (int nt = 0; nt < 16; nt++) {
            uint2 bh = wh[nt * 32];
            uint2 bl = wl[nt * 32];
            mma16(acc[nt], ah, bh.x, bh.y);   // hh
            mma16(acc[nt], al, bh.x, bh.y);   // lh
            mma16(acc[nt], ah, bl.x, bl.y);   // hl
        }
    }

    const int m0 = bm + r0;
    const int m1 = m0 + 8;
    const int which = blockIdx.y ? 2 : 0;
    float s0 = (m0 < NN) ? g_norm[which][m0] : 1.f;
    float s1 = (m1 < NN) ? g_norm[which][m1] : 1.f;
    __half2* O = blockIdx.y ? g_H1Bh : g_H1h;
    const int hc = lane & 3;
#pragma unroll
    for (int nt = 0; nt < 16; nt++) {
        int hcol = nt * 4 + hc;
        if (m0 < NN) O[(size_t)m0 * 64 + hcol] = __floats2half2_rn(acc[nt][0] * s0, acc[nt][1] * s0);
        if (m1 < NN) O[(size_t)m1 * 64 + hcol] = __floats2half2_rn(acc[nt][2] * s1, acc[nt][3] * s1);
    }
}

// ---------------- GEMM out: agg2 (fp16) @ W2 + b2 -> fp32 out ----------------
#define XH_STRIDE 68

__global__ __launch_bounds__(256, 2) void k_gemm_out(const float* __restrict__ b2,
                                                     float* __restrict__ out, int boff) {
    extern __shared__ uint32_t xh[];   // [128][XH_STRIDE] half2 words
    const int t = threadIdx.x, wid = t >> 5, lane = t & 31;
    const int bm = (blockIdx.x + boff) * 128;
    const uint32_t* __restrict__ Ah = (const uint32_t*)g_H1Bh;   // agg2

    for (int i = t; i < 128 * 16; i += 256) {
        int r = i >> 4, c4 = (i & 15) * 4;
        uint4 v = make_uint4(0u, 0u, 0u, 0u);
        if (bm + r < NN) v = *(const uint4*)(Ah + (size_t)(bm + r) * 64 + c4);
        *(uint4*)&xh[r * XH_STRIDE + c4] = v;
    }
    __syncthreads();

    const uint32_t* __restrict__ Wh = g_Wp[4];
    const uint32_t* __restrict__ Wl = g_Wp[5];

    float acc[16][4];
#pragma unroll
    for (int nt = 0; nt < 16; nt++)
#pragma unroll
        for (int j = 0; j < 4; j++) acc[nt][j] = 0.f;

    const int r0 = wid * 16 + (lane >> 2);
    const int cw = lane & 3;

#pragma unroll
    for (int ks = 0; ks < 8; ks++) {
        uint32_t ah[4];
        ah[0] = xh[r0 * XH_STRIDE + ks * 8 + cw];
        ah[1] = xh[(r0 + 8) * XH_STRIDE + ks * 8 + cw];
        ah[2] = xh[r0 * XH_STRIDE + ks * 8 + 4 + cw];
        ah[3] = xh[(r0 + 8) * XH_STRIDE + ks * 8 + 4 + cw];

        const uint2* wh = (const uint2*)(Wh + ks * 1024) + lane;
        const uint2* wl = (const uint2*)(Wl + ks * 1024) + lane;
#pragma unroll
        for (int nt = 0; nt < 16; nt++) {
            uint2 bh = wh[nt * 32];
            uint2 bl = wl[nt * 32];
            mma16(acc[nt], ah, bh.x, bh.y);   // A * W_hi
            mma16(acc[nt], ah, bl.x, bl.y);   // A * W_lo
        }
    }

    const int m0 = bm + r0;
    const int m1 = m0 + 8;
    const int colb = 2 * (lane & 3);
#pragma unroll
    for (int nt = 0; nt < 16; nt++) {
        int col = nt * 8 + colb;
        float2 bb = *(const float2*)(b2 + col);
        if (m0 < NN)
            *(float2*)&out[(size_t)m0 * FD + col] = make_float2(acc[nt][0] + bb.x, acc[nt][1] + bb.y);
        if (m1 < NN)
            *(float2*)&out[(size_t)m1 * FD + col] = make_float2(acc[nt][2] + bb.x, acc[nt][3] + bb.y);
    }
}

// ---------------- SpMM: 32 lanes (uint2 = 4 halves) x 8 nodes per block ----------------
__device__ __forceinline__ float4 gather_h32(const uint2* __restrict__ H,
                                             const int* __restrict__ col,
                                             int e, int e1, int lane) {
    float a0 = 0.f, a1 = 0.f, a2 = 0.f, a3 = 0.f;
    for (; e + 4 <= e1; e += 4) {
        int s0 = col[e], s1 = col[e + 1], s2 = col[e + 2], s3 = col[e + 3];
        uint2 u0 = H[(size_t)s0 * 32 + lane];
        uint2 u1 = H[(size_t)s1 * 32 + lane];
        uint2 u2 = H[(size_t)s2 * 32 + lane];
        uint2 u3 = H[(size_t)s3 * 32 + lane];
        float2 p, q;
        p = __half22float2(*(__half2*)&u0.x); q = __half22float2(*(__half2*)&u0.y);
        a0 += p.x; a1 += p.y; a2 += q.x; a3 += q.y;
        p = __half22float2(*(__half2*)&u1.x); q = __half22float2(*(__half2*)&u1.y);
        a0 += p.x; a1 += p.y; a2 += q.x; a3 += q.y;
        p = __half22float2(*(__half2*)&u2.x); q = __half22float2(*(__half2*)&u2.y);
        a0 += p.x; a1 += p.y; a2 += q.x; a3 += q.y;
        p = __half22float2(*(__half2*)&u3.x); q = __half22float2(*(__half2*)&u3.y);
        a0 += p.x; a1 += p.y; a2 += q.x; a3 += q.y;
    }
    for (; e < e1; e++) {
        uint2 u = H[(size_t)col[e] * 32 + lane];
        float2 p = __half22float2(*(__half2*)&u.x);
        float2 q = __half22float2(*(__half2*)&u.y);
        a0 += p.x; a1 += p.y; a2 += q.x; a3 += q.y;
    }
    return make_float4(a0, a1, a2, a3);
}

__global__ void k_spmm1(const float* __restrict__ b1i, const float* __restrict__ b1b) {
    int v = blockIdx.x * 8 + threadIdx.y;
    if (v >= NN) return;
    int lane = threadIdx.x;
    float4 ai = gather_h32((const uint2*)g_H1h,  g_col[0], g_rowptr[0][v], g_rowptr[0][v + 1], lane);
    float4 ab = gather_h32((const uint2*)g_H1Bh, g_col[1], g_rowptr[1][v], g_rowptr[1][v + 1], lane);
    float n1 = g_norm[1][v], n3 = g_norm[3][v], n0 = g_norm[0][v];
    float4 bi = *(const float4*)(b1i + 4 * lane);
    float4 bb = *(const float4*)(b1b + 4 * lane);
    float h0 = fmaxf(ai.x * n1 + bi.x, 0.f) + fmaxf(ab.x * n3 + bb.x, 0.f);
    float h1 = fmaxf(ai.y * n1 + bi.y, 0.f) + fmaxf(ab.y * n3 + bb.y, 0.f);
    float h2 = fmaxf(ai.z * n1 + bi.z, 0.f) + fmaxf(ab.z * n3 + bb.z, 0.f);
    float h3 = fmaxf(ai.w * n1 + bi.w, 0.f) + fmaxf(ab.w * n3 + bb.w, 0.f);
    __half2 o0 = __floats2half2_rn(h0 * n0, h1 * n0);
    __half2 o1 = __floats2half2_rn(h2 * n0, h3 * n0);
    uint2 o = make_uint2(*(uint32_t*)&o0, *(uint32_t*)&o1);
    ((uint2*)g_Hh)[(size_t)v * 32 + lane] = o;
}

// gather g_Hh over interacts, scale by n1, write fp16 agg into g_H1Bh (reused)
__global__ void k_spmm2(int voff) {
    int v = voff + blockIdx.x * 8 + threadIdx.y;
    if (v >= NN) return;
    int lane = threadIdx.x;
    float4 a = gather_h32((const uint2*)g_Hh, g_col[0], g_rowptr[0][v], g_rowptr[0][v + 1], lane);
    float n1 = g_norm[1][v];
    __half2 o0 = __floats2half2_rn(a.x * n1, a.y * n1);
    __half2 o1 = __floats2half2_rn(a.z * n1, a.w * n1);
    uint2 o = make_uint2(*(uint32_t*)&o0, *(uint32_t*)&o1);
    ((uint2*)g_H1Bh)[(size_t)v * 32 + lane] = o;
}

// ---------------- launch ----------------
extern "C" void kernel_launch(void* const* d_in, const int* in_sizes, int n_in,
                              void* d_out, int out_size) {
    (void)in_sizes; (void)n_in; (void)out_size;
    const float* x    = (const float*)d_in[0];
    const int*   si   = (const int*)d_in[1];
    const int*   di   = (const int*)d_in[2];
    const int*   sb   = (const int*)d_in[3];
    const int*   db   = (const int*)d_in[4];
    const float* W1i  = (const float*)d_in[5];
    const float* b1i  = (const float*)d_in[6];
    const float* W1b  = (const float*)d_in[7];
    const float* b1b  = (const float*)d_in[8];
    const float* W2   = (const float*)d_in[9];
    const float* b2   = (const float*)d_in[10];
    float* out = (float*)d_out;

    const int XS_BYTES = 128 * XS_STRIDE * sizeof(float);     // 67584
    const int XH_BYTES = 128 * XH_STRIDE * sizeof(uint32_t);  // 34816

    static cudaStream_t s2 = nullptr;
    static cudaEvent_t evF = nullptr, evA = nullptr, ev1 = nullptr, ev2 = nullptr, evG = nullptr;
    static int init_done = 0;
    if (!init_done) {   // first (uncaptured) correctness call only
        cudaFuncSetAttribute(k_gemm0, cudaFuncAttributeMaxDynamicSharedMemorySize, XS_BYTES);
        cudaStreamCreateWithFlags(&s2, cudaStreamNonBlocking);
        cudaEventCreateWithFlags(&evF, cudaEventDisableTiming);
        cudaEventCreateWithFlags(&evA, cudaEventDisableTiming);
        cudaEventCreateWithFlags(&ev1, cudaEventDisableTiming);
        cudaEventCreateWithFlags(&ev2, cudaEventDisableTiming);
        cudaEventCreateWithFlags(&evG, cudaEventDisableTiming);
        init_done = 1;
    }

    const int gblk = (NN + 127) / 128;   // 782
    const dim3 sblk(32, 8);

    // common prefix (stream 0)
    k_zero<<<(4 * NN + 255) / 256, 256>>>();
    k_hist<<<(EE + 255) / 256, 256>>>(si, di, sb, db);
    k_prepW<<<(3 * 8192 + 255) / 256, 256>>>(W1i, W1b, W2);
    k_norm<<<(NN + 255) / 256, 256>>>();

    // fork: GEMM0 (tensor-bound) on s2, CSR build (memory-bound) on stream 0
    cudaEventRecord(evF, 0);
    cudaStreamWaitEvent(s2, evF, 0);
    k_gemm0<<<dim3(gblk, 2), 256, XS_BYTES, s2>>>(x);   // g_H1h, g_H1Bh

    {
        dim3 ga(NCH, 2);
        k_scanA<<<ga, 256>>>();
        k_scanB<<<2, 128>>>();
        k_scanC<<<ga, CHUNK>>>();
    }
    k_csrfill<<<(EE + 255) / 256, 256>>>(si, di, sb, db);

    // join GEMM0
    cudaEventRecord(evA, s2);
    cudaStreamWaitEvent(0, evA, 0);

    // conv1 combine
    k_spmm1<<<(NN + 7) / 8, sblk>>>(b1i, b1b);          // g_Hh (fp16)

    // tail: spmm2 (gather, L2-bound) chunked; gemm_out (tensor-bound) overlaps on s2
    k_spmm2<<<NODES_C0 / 8, sblk>>>(0);                 // agg2 nodes [0, 50048)
    cudaEventRecord(ev1, 0);
    k_spmm2<<<(NN - NODES_C0 + 7) / 8, sblk>>>(NODES_C0);
    cudaEventRecord(ev2, 0);

    cudaStreamWaitEvent(s2, ev1, 0);
    k_gemm_out<<<GBLK_C0, 256, XH_BYTES, s2>>>(b2, out, 0);
    cudaStreamWaitEvent(s2, ev2, 0);
    k_gemm_out<<<gblk - GBLK_C0, 256, XH_BYTES, s2>>>(b2, out, GBLK_C0);

    // final join back to origin stream
    cudaEventRecord(evG, s2);
    cudaStreamWaitEvent(0, evG, 0);
}